// round 4
// baseline (speedup 1.0000x reference)
#include <cuda_runtime.h>
#include <math.h>

// Problem constants: B=64, Q=900, C=256, T=200
#define B_  64
#define Q_  900
#define C_  256
#define T_  200
#define WARPS 4            // 128 threads
#define QPW   2
#define QTILE (WARPS*QPW)  // 8 q rows per block
#define EPSV 1e-6f

__device__ __forceinline__ float rcpa(float x) {
    float y;
    asm("rcp.approx.ftz.f32 %0, %1;" : "=f"(y) : "f"(x));
    return y;
}

struct QState {
    float x0, y0, x1, y1;  // xyxy
    float sx, sy;          // x0+x1, y0+y1
    float w, h, a;
};

// cost for one (query, target) pair, given unnormalized prob gather pexp and inv
__device__ __forceinline__ float cost_one(
    const QState& q, float inv, float pexp, float4 txy,
    float tsx, float tsy, float tw, float th, float ta)
{
    float dsx = q.sx - tsx, dsy = q.sy - tsy;
    float dw  = q.w - tw,   dh  = q.h - th;
    float l1a = fabsf(dsx) + fabsf(dsy);
    float l1b = fabsf(dw)  + fabsf(dh);

    float iw = fminf(q.x1, txy.z) - fmaxf(q.x0, txy.x);
    float ih = fminf(q.y1, txy.w) - fmaxf(q.y0, txy.y);
    float inter = fmaxf(iw, 0.0f) * fmaxf(ih, 0.0f);
    float uni   = (q.a + ta) - inter;
    float cw = (q.w + tw) - iw;      // >= 0 by min+max identity
    float ch = (q.h + th) - ih;
    float areac = cw * ch;

    float ru = rcpa(uni);
    float rc = rcpa(areac);
    // cost = (2 - p) + 2.5*l1a + 5*l1b - 2*(inter/uni + uni/areac),  p = pexp*inv
    float base = fmaf(-inv, pexp, 2.0f);
    base = fmaf(2.5f, l1a, fmaf(5.0f, l1b, base));
    float tsum = fmaf(uni, rc, inter * ru);
    return fmaf(-2.0f, tsum, base);
}

__global__ __launch_bounds__(128, 10)
void matcher_kernel(const float* __restrict__ logits,   // [B,Q,C]
                    const float* __restrict__ pboxes,   // [B,Q,4]
                    const int*   __restrict__ tlabels,  // [B,T]
                    const float* __restrict__ tboxes,   // [B,T,4]
                    float*       __restrict__ out)      // [B,Q,T]
{
    __shared__ float  s_exp[QTILE][C_];   // 8 KB: UNNORMALIZED exp rows
    __shared__ float4 s_txy[T_];          // 3.2 KB
    __shared__ int2   s_tloff[(T_ + 1) / 2];  // label byte-offset pairs

    const int b   = blockIdx.y;
    const int tid = threadIdx.x;

    // ---- Phase A: stage targets ----
    for (int t = tid; t < T_; t += 128) {
        float4 bx = reinterpret_cast<const float4*>(tboxes)[b * T_ + t];
        float cx = fminf(fmaxf(bx.x, 0.0f), 1.0f);   // NaN -> 0 via fmaxf
        float cy = fminf(fmaxf(bx.y, 0.0f), 1.0f);
        float w  = fminf(fmaxf(bx.z, EPSV), 1.0f);
        float h  = fminf(fmaxf(bx.w, EPSV), 1.0f);
        s_txy[t] = make_float4(cx - 0.5f * w, cy - 0.5f * h,
                               cx + 0.5f * w, cy + 0.5f * h);
        reinterpret_cast<int*>(s_tloff)[t] = tlabels[b * T_ + t] * 4;
    }

    const int warp  = tid >> 5;
    const int lane  = tid & 31;
    const int qbase = blockIdx.x * QTILE + warp * QPW;

    // ---- Phase B: exp rows + inv-sum (no max-sub; inputs bounded after nan_to_num) ----
    QState qs[QPW];
    float  inv[QPW];
    bool   qv[QPW];

    #pragma unroll
    for (int r = 0; r < QPW; r++) {
        const int q = qbase + r;
        qv[r] = (q < Q_);
        if (qv[r]) {
            const float* lrow = logits + ((long)(b * Q_ + q)) * C_;
            float4 v0 = reinterpret_cast<const float4*>(lrow)[lane];
            float4 v1 = reinterpret_cast<const float4*>(lrow)[lane + 32];
            float* pr = s_exp[warp * QPW + r];
            float s = 0.0f;

            // half 1: sanitize, exp, store unnormalized
            {
                float e0 = __expf((fabsf(v0.x) < INFINITY) ? v0.x : 0.0f);
                float e1 = __expf((fabsf(v0.y) < INFINITY) ? v0.y : 0.0f);
                float e2 = __expf((fabsf(v0.z) < INFINITY) ? v0.z : 0.0f);
                float e3 = __expf((fabsf(v0.w) < INFINITY) ? v0.w : 0.0f);
                s = ((e0 + e1) + (e2 + e3));
                reinterpret_cast<float4*>(pr)[lane] = make_float4(e0, e1, e2, e3);
            }
            // half 2
            {
                float e0 = __expf((fabsf(v1.x) < INFINITY) ? v1.x : 0.0f);
                float e1 = __expf((fabsf(v1.y) < INFINITY) ? v1.y : 0.0f);
                float e2 = __expf((fabsf(v1.z) < INFINITY) ? v1.z : 0.0f);
                float e3 = __expf((fabsf(v1.w) < INFINITY) ? v1.w : 0.0f);
                s += ((e0 + e1) + (e2 + e3));
                reinterpret_cast<float4*>(pr)[lane + 32] = make_float4(e0, e1, e2, e3);
            }
            #pragma unroll
            for (int o = 16; o; o >>= 1) s += __shfl_xor_sync(0xFFFFFFFFu, s, o);
            inv[r] = rcpa(s);

            float4 qb = reinterpret_cast<const float4*>(pboxes)[b * Q_ + q];
            float cx = fminf(fmaxf(qb.x, 0.0f), 1.0f);
            float cy = fminf(fmaxf(qb.y, 0.0f), 1.0f);
            float w  = fminf(fmaxf(qb.z, EPSV), 1.0f);
            float h  = fminf(fmaxf(qb.w, EPSV), 1.0f);
            qs[r].x0 = cx - 0.5f * w;  qs[r].y0 = cy - 0.5f * h;
            qs[r].x1 = cx + 0.5f * w;  qs[r].y1 = cy + 0.5f * h;
            qs[r].sx = qs[r].x0 + qs[r].x1;
            qs[r].sy = qs[r].y0 + qs[r].y1;
            qs[r].w = w; qs[r].h = h; qs[r].a = w * h;
        } else {
            inv[r] = 0.0f;
        }
    }

    __syncthreads();

    // ---- Phase C: pair-process targets, float2 stores ----
    const float* pr0 = s_exp[warp * QPW + 0];
    const float* pr1 = s_exp[warp * QPW + 1];
    float* orow0 = out + ((long)(b * Q_ + qbase + 0)) * T_;
    float* orow1 = out + ((long)(b * Q_ + qbase + 1)) * T_;

    #pragma unroll
    for (int k = 0; k < 4; k++) {
        const int tp = lane + 32 * k;      // pair index
        const int t0 = 2 * tp;
        if (t0 < T_) {
            float4 A = s_txy[t0];
            float4 Bx = s_txy[t0 + 1];
            int2  off = s_tloff[tp];

            float Atsx = A.x + A.z,  Atsy = A.y + A.w;
            float Atw  = A.z - A.x,  Ath  = A.w - A.y;
            float Ata  = Atw * Ath;
            float Btsx = Bx.x + Bx.z, Btsy = Bx.y + Bx.w;
            float Btw  = Bx.z - Bx.x, Bth  = Bx.w - Bx.y;
            float Bta  = Btw * Bth;

            if (qv[0]) {
                float pA = *reinterpret_cast<const float*>(
                               reinterpret_cast<const char*>(pr0) + off.x);
                float pB = *reinterpret_cast<const float*>(
                               reinterpret_cast<const char*>(pr0) + off.y);
                float c0 = cost_one(qs[0], inv[0], pA, A,  Atsx, Atsy, Atw, Ath, Ata);
                float c1 = cost_one(qs[0], inv[0], pB, Bx, Btsx, Btsy, Btw, Bth, Bta);
                *reinterpret_cast<float2*>(orow0 + t0) = make_float2(c0, c1);
            }
            if (qv[1]) {
                float pA = *reinterpret_cast<const float*>(
                               reinterpret_cast<const char*>(pr1) + off.x);
                float pB = *reinterpret_cast<const float*>(
                               reinterpret_cast<const char*>(pr1) + off.y);
                float c0 = cost_one(qs[1], inv[1], pA, A,  Atsx, Atsy, Atw, Ath, Ata);
                float c1 = cost_one(qs[1], inv[1], pB, Bx, Btsx, Btsy, Btw, Bth, Bta);
                *reinterpret_cast<float2*>(orow1 + t0) = make_float2(c0, c1);
            }
        }
    }
}

extern "C" void kernel_launch(void* const* d_in, const int* in_sizes, int n_in,
                              void* d_out, int out_size)
{
    const float* logits  = (const float*)d_in[0];
    const float* pboxes  = (const float*)d_in[1];
    const int*   tlabels = (const int*)  d_in[2];
    const float* tboxes  = (const float*)d_in[3];
    float*       out     = (float*)d_out;

    dim3 grid((Q_ + QTILE - 1) / QTILE, B_);
    matcher_kernel<<<grid, 128>>>(logits, pboxes, tlabels, tboxes, out);
}

// round 5
// speedup vs baseline: 1.2800x; 1.2800x over previous
#include <cuda_runtime.h>
#include <math.h>

// Problem constants: B=64, Q=900, C=256, T=200
#define B_  64
#define Q_  900
#define C_  256
#define T_  200
#define WARPS 4            // 128 threads
#define QPW   2
#define QTILE (WARPS*QPW)  // 8 q rows per block
#define EPSV 1e-6f

__device__ __forceinline__ float rcpa(float x) {
    float y;
    asm("rcp.approx.ftz.f32 %0, %1;" : "=f"(y) : "f"(x));
    return y;
}

__device__ __forceinline__ float san(float v) {   // nan_to_num(0,0,0)
    return (fabsf(v) < INFINITY) ? v : 0.0f;
}

struct QState {
    float x0, y0, x1, y1;  // xyxy
    float sx, sy;          // x0+x1, y0+y1
    float w, h, a;
};

__device__ __forceinline__ QState make_qstate(float4 qb) {
    QState s;
    float cx = fminf(fmaxf(qb.x, 0.0f), 1.0f);
    float cy = fminf(fmaxf(qb.y, 0.0f), 1.0f);
    float w  = fminf(fmaxf(qb.z, EPSV), 1.0f);
    float h  = fminf(fmaxf(qb.w, EPSV), 1.0f);
    s.x0 = cx - 0.5f * w;  s.y0 = cy - 0.5f * h;
    s.x1 = cx + 0.5f * w;  s.y1 = cy + 0.5f * h;
    s.sx = s.x0 + s.x1;    s.sy = s.y0 + s.y1;
    s.w = w; s.h = h; s.a = w * h;
    return s;
}

__device__ __forceinline__ float cost_one(
    const QState& q, float inv, float pexp, float4 txy,
    float tsx, float tsy, float tw, float th, float ta)
{
    float l1a = fabsf(q.sx - tsx) + fabsf(q.sy - tsy);
    float l1b = fabsf(q.w - tw)   + fabsf(q.h - th);

    float iw = fminf(q.x1, txy.z) - fmaxf(q.x0, txy.x);
    float ih = fminf(q.y1, txy.w) - fmaxf(q.y0, txy.y);
    float inter = fmaxf(iw, 0.0f) * fmaxf(ih, 0.0f);
    float uni   = (q.a + ta) - inter;
    float cw = (q.w + tw) - iw;      // >= 0 by min+max identity
    float ch = (q.h + th) - ih;
    float areac = cw * ch;

    float ru = rcpa(uni);
    float rc = rcpa(areac);
    // cost = (2 - pexp*inv) + 2.5*l1a + 5*l1b - 2*(inter/uni + uni/areac)
    float base = fmaf(-inv, pexp, 2.0f);
    base = fmaf(2.5f, l1a, fmaf(5.0f, l1b, base));
    float tsum = fmaf(uni, rc, inter * ru);
    return fmaf(-2.0f, tsum, base);
}

__global__ __launch_bounds__(128, 10)
void matcher_kernel(const float* __restrict__ logits,   // [B,Q,C]
                    const float* __restrict__ pboxes,   // [B,Q,4]
                    const int*   __restrict__ tlabels,  // [B,T]
                    const float* __restrict__ tboxes,   // [B,T,4]
                    float*       __restrict__ out)      // [B,Q,T]
{
    __shared__ float  s_exp[QTILE][C_];   // 8 KB: UNNORMALIZED exp rows
    __shared__ float4 s_txy[T_];          // 3.2 KB
    __shared__ int    s_tloff[T_];        // label byte offsets

    const int b   = blockIdx.y;
    const int tid = threadIdx.x;
    const int warp  = tid >> 5;
    const int lane  = tid & 31;
    const int qbase = blockIdx.x * QTILE + warp * QPW;

    // Branchless row indices (loads always execute; stores are guarded)
    const int q0 = min(qbase + 0, Q_ - 1);
    const int q1 = min(qbase + 1, Q_ - 1);

    // ---- Front-batched global loads (MLP) ----
    const float4* l0 = reinterpret_cast<const float4*>(logits + ((long)(b * Q_ + q0)) * C_);
    const float4* l1 = reinterpret_cast<const float4*>(logits + ((long)(b * Q_ + q1)) * C_);
    float4 va0 = l0[lane];
    float4 va1 = l0[lane + 32];
    float4 vb0 = l1[lane];
    float4 vb1 = l1[lane + 32];
    float4 qbx0 = reinterpret_cast<const float4*>(pboxes)[b * Q_ + q0];
    float4 qbx1 = reinterpret_cast<const float4*>(pboxes)[b * Q_ + q1];

    // ---- Phase A: stage targets (runs while logit loads are in flight) ----
    for (int t = tid; t < T_; t += 128) {
        float4 bx = reinterpret_cast<const float4*>(tboxes)[b * T_ + t];
        float cx = fminf(fmaxf(bx.x, 0.0f), 1.0f);
        float cy = fminf(fmaxf(bx.y, 0.0f), 1.0f);
        float w  = fminf(fmaxf(bx.z, EPSV), 1.0f);
        float h  = fminf(fmaxf(bx.w, EPSV), 1.0f);
        s_txy[t]   = make_float4(cx - 0.5f * w, cy - 0.5f * h,
                                 cx + 0.5f * w, cy + 0.5f * h);
        s_tloff[t] = tlabels[b * T_ + t] * 4;
    }

    // ---- Phase B: exp rows (unnormalized) + interleaved reductions ----
    float* pr0 = s_exp[warp * QPW + 0];
    float* pr1 = s_exp[warp * QPW + 1];

    float ea0 = __expf(san(va0.x)), ea1 = __expf(san(va0.y));
    float ea2 = __expf(san(va0.z)), ea3 = __expf(san(va0.w));
    float ea4 = __expf(san(va1.x)), ea5 = __expf(san(va1.y));
    float ea6 = __expf(san(va1.z)), ea7 = __expf(san(va1.w));
    float eb0 = __expf(san(vb0.x)), eb1 = __expf(san(vb0.y));
    float eb2 = __expf(san(vb0.z)), eb3 = __expf(san(vb0.w));
    float eb4 = __expf(san(vb1.x)), eb5 = __expf(san(vb1.y));
    float eb6 = __expf(san(vb1.z)), eb7 = __expf(san(vb1.w));

    reinterpret_cast<float4*>(pr0)[lane]      = make_float4(ea0, ea1, ea2, ea3);
    reinterpret_cast<float4*>(pr0)[lane + 32] = make_float4(ea4, ea5, ea6, ea7);
    reinterpret_cast<float4*>(pr1)[lane]      = make_float4(eb0, eb1, eb2, eb3);
    reinterpret_cast<float4*>(pr1)[lane + 32] = make_float4(eb4, eb5, eb6, eb7);

    float s0 = ((ea0 + ea1) + (ea2 + ea3)) + ((ea4 + ea5) + (ea6 + ea7));
    float s1 = ((eb0 + eb1) + (eb2 + eb3)) + ((eb4 + eb5) + (eb6 + eb7));
    #pragma unroll
    for (int o = 16; o; o >>= 1) {   // two independent chains interleave (ILP 2)
        s0 += __shfl_xor_sync(0xFFFFFFFFu, s0, o);
        s1 += __shfl_xor_sync(0xFFFFFFFFu, s1, o);
    }
    float inv0 = rcpa(s0);
    float inv1 = rcpa(s1);

    QState qs0 = make_qstate(qbx0);
    QState qs1 = make_qstate(qbx1);

    __syncthreads();

    // ---- Phase C: stride-32 sweep (conflict-free LDS), guarded stores ----
    const bool st0 = (qbase + 0 < Q_);
    const bool st1 = (qbase + 1 < Q_);
    float* orow0 = out + ((long)(b * Q_ + qbase + 0)) * T_;
    float* orow1 = out + ((long)(b * Q_ + qbase + 1)) * T_;

    #pragma unroll
    for (int k = 0; k < (T_ + 31) / 32; k++) {
        const int t = lane + 32 * k;
        if (t < T_) {
            float4 txy = s_txy[t];
            int    off = s_tloff[t];
            float tsx = txy.x + txy.z;
            float tsy = txy.y + txy.w;
            float tw  = txy.z - txy.x;
            float th  = txy.w - txy.y;
            float ta  = tw * th;

            float p0 = *reinterpret_cast<const float*>(
                           reinterpret_cast<const char*>(pr0) + off);
            float p1 = *reinterpret_cast<const float*>(
                           reinterpret_cast<const char*>(pr1) + off);

            float c0 = cost_one(qs0, inv0, p0, txy, tsx, tsy, tw, th, ta);
            float c1 = cost_one(qs1, inv1, p1, txy, tsx, tsy, tw, th, ta);

            if (st0) orow0[t] = c0;
            if (st1) orow1[t] = c1;
        }
    }
}

extern "C" void kernel_launch(void* const* d_in, const int* in_sizes, int n_in,
                              void* d_out, int out_size)
{
    const float* logits  = (const float*)d_in[0];
    const float* pboxes  = (const float*)d_in[1];
    const int*   tlabels = (const int*)  d_in[2];
    const float* tboxes  = (const float*)d_in[3];
    float*       out     = (float*)d_out;

    dim3 grid((Q_ + QTILE - 1) / QTILE, B_);
    matcher_kernel<<<grid, 128>>>(logits, pboxes, tlabels, tboxes, out);
}